// round 11
// baseline (speedup 1.0000x reference)
#include <cuda_runtime.h>
#include <cstdint>

#define B_  2
#define T_  2048
#define HD  64
#define NH  8
#define DM  512
#define ED  512
#define EV  388
#define EVP 448      // Wl padded width

// ---------------- scratch ----------------
__device__ unsigned g_qh  [B_*T_*HD];   // tf32 bits, pre-scaled by 0.125
__device__ unsigned g_kh  [B_*T_*HD];   // tf32 bits
__device__ unsigned g_vh  [B_*T_*HD];   // tf32 bits
__device__ unsigned g_Etf [NH*T_*HD];   // tf32 bits
__device__ unsigned g_Wotf[DM*ED];      // tf32 bits
__device__ unsigned g_Wltf[ED*EVP];     // tf32 bits, zero-padded cols
__device__ unsigned g_ctx [B_*T_*DM];   // tf32 bits (attn out)
__device__ unsigned g_hid [B_*T_*ED];   // tf32 bits (relu out)

// ---------------- tf32 / async helpers ----------------
__device__ __forceinline__ unsigned f2tf(float f) {
  unsigned u; asm("cvt.rna.tf32.f32 %0, %1;" : "=r"(u) : "f"(f)); return u;
}
__device__ __forceinline__ unsigned u2tf(unsigned raw) {
  return f2tf(__uint_as_float(raw));
}
__device__ __forceinline__ void mma8(float4& d, unsigned a0, unsigned a1, unsigned a2, unsigned a3,
                                     unsigned b0, unsigned b1) {
  asm volatile("mma.sync.aligned.m16n8k8.row.col.f32.tf32.tf32.f32 "
               "{%0,%1,%2,%3}, {%4,%5,%6,%7}, {%8,%9}, {%0,%1,%2,%3};"
               : "+f"(d.x), "+f"(d.y), "+f"(d.z), "+f"(d.w)
               : "r"(a0), "r"(a1), "r"(a2), "r"(a3), "r"(b0), "r"(b1));
}
__device__ __forceinline__ void cpa16(unsigned smem, const void* g) {
  asm volatile("cp.async.cg.shared.global [%0], [%1], 16;" :: "r"(smem), "l"(g));
}
#define CPA_COMMIT() asm volatile("cp.async.commit_group;")
#define CPA_WAIT(N)  asm volatile("cp.async.wait_group %0;" :: "n"(N) : "memory")
__device__ __forceinline__ void cpa_wait_all() {
  CPA_COMMIT(); CPA_WAIT(0);
}

// ---------------- one-shot fused converter (verified r10) ------------------
#define NE4  (NH*T_*HD/4)    // 262144
#define NWO4 (DM*ED/4)       // 65536
#define NWL4 (ED*EVP/4)      // 57344
__global__ void cvt_all(const float* __restrict__ E, const float* __restrict__ Wo,
                        const float* __restrict__ Wl,
                        unsigned* __restrict__ Etf, unsigned* __restrict__ Wotf,
                        unsigned* __restrict__ Wltf) {
  const int i = blockIdx.x * 256 + threadIdx.x;
  if (i < NE4) {
    float4 f = ((const float4*)E)[i];
    ((uint4*)Etf)[i] = make_uint4(f2tf(f.x), f2tf(f.y), f2tf(f.z), f2tf(f.w));
  } else if (i < NE4 + NWO4) {
    const int j = i - NE4;
    float4 f = ((const float4*)Wo)[j];
    ((uint4*)Wotf)[j] = make_uint4(f2tf(f.x), f2tf(f.y), f2tf(f.z), f2tf(f.w));
  } else if (i < NE4 + NWO4 + NWL4) {
    const int j = i - NE4 - NWO4;
    const int row = (j * 4) / EVP, col = (j * 4) % EVP;
    uint4 u = make_uint4(0u, 0u, 0u, 0u);
    if (col < EV) {
      float4 f = *(const float4*)(Wl + (size_t)row * EV + col);
      u = make_uint4(f2tf(f.x), f2tf(f.y), f2tf(f.z), f2tf(f.w));
    }
    ((uint4*)Wltf)[j] = u;
  }
}

// ================= gemm4: m64n64 tiles, tf32-in, 3-stage cp.async ==========
// 8 warps 4(m16) x 2(n32); grid = (M/64, Np/64) -> 512/448 CTAs (full chip).
#define G4S 2368   // words per stage: A 64*20=1280 + B 16*68=1088
template<bool RELU, bool TF32OUT>
__launch_bounds__(256)
__global__ void gemm4(const unsigned* __restrict__ A, const unsigned* __restrict__ Bm,
                      const float* __restrict__ bias, void* __restrict__ Cv,
                      int M, int N, int Np, int K, float oscale) {
  __shared__ unsigned sm[3 * G4S];
  const int tid = threadIdx.x;
  const int lane = tid & 31, wid = tid >> 5;
  const int wM = wid & 3, wN = wid >> 2;
  const int g = lane >> 2, tg = lane & 3;
  const int m0 = blockIdx.x * 64, n0 = blockIdx.y * 64;
  const int ar = tid >> 2, ac = (tid & 3) * 4;
  const int bk = tid >> 4, bn = (tid & 15) * 4;
  const unsigned s_base = (unsigned)__cvta_generic_to_shared(sm);

  const int NT = K >> 4;
#define G4_ISSUE(KT) do {                                                   \
    const int _k0 = (KT) * 16;                                              \
    const unsigned _st = s_base + ((KT) % 3) * (G4S * 4);                   \
    cpa16(_st + (unsigned)(ar*20+ac)*4u, A + (size_t)(m0+ar)*K + _k0+ac);   \
    cpa16(_st + (unsigned)(1280 + bk*68+bn)*4u,                             \
          Bm + (size_t)(_k0+bk)*Np + n0+bn);                                \
  } while (0)

  G4_ISSUE(0); CPA_COMMIT();
  G4_ISSUE(1); CPA_COMMIT();

  float4 acc[4];
#pragma unroll
  for (int nf = 0; nf < 4; nf++) acc[nf] = make_float4(0.f, 0.f, 0.f, 0.f);

  for (int kt = 0; kt < NT; kt++) {
    CPA_WAIT(1);
    __syncthreads();
    if (kt + 2 < NT) G4_ISSUE(kt + 2);
    CPA_COMMIT();
    const unsigned* Ac = sm + (kt % 3) * G4S;
    const unsigned* Bc = Ac + 1280;
#pragma unroll
    for (int kb = 0; kb < 2; kb++) {
      const int kk = kb * 8;
      const int r = wM * 16 + g;
      const unsigned a0 = Ac[ r      * 20 + kk + tg];
      const unsigned a1 = Ac[(r + 8) * 20 + kk + tg];
      const unsigned a2 = Ac[ r      * 20 + kk + tg + 4];
      const unsigned a3 = Ac[(r + 8) * 20 + kk + tg + 4];
#pragma unroll
      for (int nf = 0; nf < 4; nf++) {
        const int n = wN * 32 + nf * 8 + g;
        mma8(acc[nf], a0, a1, a2, a3, Bc[(kk + tg) * 68 + n], Bc[(kk + tg + 4) * 68 + n]);
      }
    }
  }

  {
    const int r1 = m0 + wM * 16 + g, r2 = r1 + 8;
#pragma unroll
    for (int nf = 0; nf < 4; nf++) {
      const int c = n0 + wN * 32 + nf * 8 + 2 * tg;
      const float4 a = acc[nf];
      if (c < N) {
        const float bv = bias[c];
        float v1 = a.x + bv, v2 = a.z + bv;
        if (RELU) { v1 = fmaxf(v1, 0.f); v2 = fmaxf(v2, 0.f); }
        if (TF32OUT) {
          ((unsigned*)Cv)[(size_t)r1 * N + c] = f2tf(v1 * oscale);
          ((unsigned*)Cv)[(size_t)r2 * N + c] = f2tf(v2 * oscale);
        } else {
          ((float*)Cv)[(size_t)r1 * N + c] = v1;
          ((float*)Cv)[(size_t)r2 * N + c] = v2;
        }
      }
      if (c + 1 < N) {
        const float bv = bias[c + 1];
        float v1 = a.y + bv, v2 = a.w + bv;
        if (RELU) { v1 = fmaxf(v1, 0.f); v2 = fmaxf(v2, 0.f); }
        if (TF32OUT) {
          ((unsigned*)Cv)[(size_t)r1 * N + c + 1] = f2tf(v1 * oscale);
          ((unsigned*)Cv)[(size_t)r2 * N + c + 1] = f2tf(v2 * oscale);
        } else {
          ((float*)Cv)[(size_t)r1 * N + c + 1] = v1;
          ((float*)Cv)[(size_t)r2 * N + c + 1] = v2;
        }
      }
    }
  }
#undef G4_ISSUE
}

// ================= proj4: m64-tile pipelined q/k/v projection (r10) ========
#define P4S 2368   // words per stage: A 64*20=1280 + B 16*68=1088
__launch_bounds__(256)
__global__ void proj4(const float* __restrict__ q, const float* __restrict__ k,
                      const float* __restrict__ v,
                      const float* __restrict__ Wq, const float* __restrict__ bq,
                      const float* __restrict__ Wk, const float* __restrict__ bk2,
                      const float* __restrict__ Wv, const float* __restrict__ bv2,
                      unsigned* __restrict__ qh, unsigned* __restrict__ kh,
                      unsigned* __restrict__ vh) {
  __shared__ unsigned sm[3 * P4S];
  const float* A; const float* Bm; const float* Bi; unsigned* Cc; float sc;
  if (blockIdx.z == 0)      { A = q; Bm = Wq; Bi = bq;  Cc = qh; sc = 0.125f; }
  else if (blockIdx.z == 1) { A = k; Bm = Wk; Bi = bk2; Cc = kh; sc = 1.f; }
  else                      { A = v; Bm = Wv; Bi = bv2; Cc = vh; sc = 1.f; }

  const int tid = threadIdx.x;
  const int lane = tid & 31, wid = tid >> 5;
  const int wM = wid & 3, wN = wid >> 2;
  const int g = lane >> 2, tg = lane & 3;
  const int m0 = blockIdx.x * 64;
  const int ar = tid >> 2, ac = (tid & 3) * 4;
  const int bk = tid >> 4, bn = (tid & 15) * 4;
  const unsigned s_base = (unsigned)__cvta_generic_to_shared(sm);

  const int NT = DM >> 4;   // 32
#define P4_ISSUE(KT) do {                                                       \
    const int _k0 = (KT) * 16;                                                  \
    const unsigned _st = s_base + ((KT) % 3) * (P4S * 4);                       \
    cpa16(_st + (unsigned)(ar*20+ac)*4u, A + (size_t)(m0+ar)*DM + _k0+ac);      \
    cpa16(_st + (unsigned)(1280 + bk*68+bn)*4u, Bm + (size_t)(_k0+bk)*HD + bn); \
  } while (0)

  P4_ISSUE(0); CPA_COMMIT();
  P4_ISSUE(1); CPA_COMMIT();

  float4 acc[4];
#pragma unroll
  for (int nf = 0; nf < 4; nf++) acc[nf] = make_float4(0.f, 0.f, 0.f, 0.f);

  for (int kt = 0; kt < NT; kt++) {
    CPA_WAIT(1);
    __syncthreads();
    if (kt + 2 < NT) P4_ISSUE(kt + 2);
    CPA_COMMIT();
    const unsigned* Ac = sm + (kt % 3) * P4S;
    const unsigned* Bc = Ac + 1280;
#pragma unroll
    for (int kb = 0; kb < 2; kb++) {
      const int kk = kb * 8;
      const int r = wM * 16 + g;
      const unsigned a0 = u2tf(Ac[ r      * 20 + kk + tg]);
      const unsigned a1 = u2tf(Ac[(r + 8) * 20 + kk + tg]);
      const unsigned a2 = u2tf(Ac[ r      * 20 + kk + tg + 4]);
      const unsigned a3 = u2tf(Ac[(r + 8) * 20 + kk + tg + 4]);
#pragma unroll
      for (int nf = 0; nf < 4; nf++) {
        const int n = wN * 32 + nf * 8 + g;
        const unsigned b0 = u2tf(Bc[(kk + tg) * 68 + n]);
        const unsigned b1 = u2tf(Bc[(kk + tg + 4) * 68 + n]);
        mma8(acc[nf], a0, a1, a2, a3, b0, b1);
      }
    }
  }

  {
    const int r1 = m0 + wM * 16 + g, r2 = r1 + 8;
#pragma unroll
    for (int nf = 0; nf < 4; nf++) {
      const int c = wN * 32 + nf * 8 + 2 * tg;   // always < 64
      const float4 a = acc[nf];
      const float bv0 = Bi[c], bv1 = Bi[c + 1];
      Cc[(size_t)r1 * HD + c]     = f2tf((a.x + bv0) * sc);
      Cc[(size_t)r2 * HD + c]     = f2tf((a.z + bv0) * sc);
      Cc[(size_t)r1 * HD + c + 1] = f2tf((a.y + bv1) * sc);
      Cc[(size_t)r2 * HD + c + 1] = f2tf((a.w + bv1) * sc);
    }
  }
#undef P4_ISSUE
}

// ===================== attention: pipelined loads (verified 263.5) =========
struct QFrag { uint4 a[8][2]; };

__device__ __forceinline__ void att_chunk_pro(const unsigned* __restrict__ Etf, unsigned* Es,
                                              float* QE, const QFrag& qf, int h, int cb,
                                              int wM, int wN, int g, int tg, int tid) {
  if (cb >= T_) return;
  const unsigned es_s = (unsigned)__cvta_generic_to_shared(Es);
#pragma unroll
  for (int p = 0; p < 8; p++) {
    const int j = p * 16 + (tid >> 4);
    const int d = (tid & 15) * 4;
    if (cb + j < T_)
      cpa16(es_s + (unsigned)(j * 68 + d) * 4u, Etf + ((size_t)(h * T_ + cb + j)) * HD + d);
    else
      *(uint4*)(Es + j * 68 + d) = make_uint4(0u, 0u, 0u, 0u);
  }
  cpa_wait_all();
  __syncthreads();
  float4 acc[2][4];
#pragma unroll
  for (int mf = 0; mf < 2; mf++)
#pragma unroll
    for (int nf = 0; nf < 4; nf++) acc[mf][nf] = make_float4(0.f, 0.f, 0.f, 0.f);
#pragma unroll
  for (int kb = 0; kb < 8; kb++) {
    const int kk = kb * 8;
#pragma unroll
    for (int nf = 0; nf < 4; nf++) {
      const int n = wN * 32 + nf * 8 + g;
      const unsigned b0 = Es[n * 68 + kk + tg];
      const unsigned b1 = Es[n * 68 + kk + tg + 4];
#pragma unroll
      for (int mf = 0; mf < 2; mf++)
        mma8(acc[mf][nf], qf.a[kb][mf].x, qf.a[kb][mf].y, qf.a[kb][mf].z, qf.a[kb][mf].w, b0, b1);
    }
  }
#pragma unroll
  for (int mf = 0; mf < 2; mf++) {
    const int tl = wM * 32 + mf * 16 + g;
#pragma unroll
    for (int nf = 0; nf < 4; nf++) {
      const int r = cb + wN * 32 + nf * 8 + 2 * tg;
      QE[ tl      * 260 + ( r      & 255)] = acc[mf][nf].x;
      QE[ tl      * 260 + ((r + 1) & 255)] = acc[mf][nf].y;
      QE[(tl + 8) * 260 + ( r      & 255)] = acc[mf][nf].z;
      QE[(tl + 8) * 260 + ((r + 1) & 255)] = acc[mf][nf].w;
    }
  }
  __syncthreads();
}

__launch_bounds__(256, 1)
__global__ void attn_kernel(const unsigned* __restrict__ qh, const unsigned* __restrict__ kh,
                            const unsigned* __restrict__ vh, const unsigned* __restrict__ Etf,
                            unsigned* __restrict__ ctx) {
  extern __shared__ unsigned smu[];
  unsigned* Qs = smu;                     // [64][68]
  unsigned* Ks = Qs + 4352;               // [128][68]
  unsigned* Vs = Ks + 8704;               // [128][68]
  unsigned* Ps = Vs + 8704;               // [64][132] P matrix
  unsigned* Es = Ps + 8448;               // [128][68] E chunk (dedicated)
  float*    QE = (float*)(Es + 8704);     // [64][260] ring
  float* sPmax = QE + 64 * 260;           // [4][64]
  float* sPsum = sPmax + 256;             // [4][64]

  const int tid = threadIdx.x;
  const int lane = tid & 31, wid = tid >> 5;
  const int wM = wid & 1, wN = wid >> 1;       // 2 x 4
  const int g = lane >> 2, tg = lane & 3;
  const int qt = (int)gridDim.x - 1 - (int)blockIdx.x;  // heavy tiles first
  const int t0 = qt * 64;
  const int b  = blockIdx.y;
  const int h  = blockIdx.z;

  {
    const unsigned qs_s = (unsigned)__cvta_generic_to_shared(Qs);
#pragma unroll
    for (int p = 0; p < 4; p++) {
      const int t = p * 16 + (tid >> 4);
      const int d = (tid & 15) * 4;
      cpa16(qs_s + (unsigned)(t * 68 + d) * 4u, qh + ((size_t)(b * T_ + t0 + t)) * HD + d);
    }
    cpa_wait_all();
  }
  __syncthreads();
  QFrag qf;
#pragma unroll
  for (int kb = 0; kb < 8; kb++) {
    const int c = kb * 8 + tg;
#pragma unroll
    for (int mf = 0; mf < 2; mf++) {
      const int row = wM * 32 + mf * 16 + g;
      qf.a[kb][mf].x = Qs[ row      * 68 + c];
      qf.a[kb][mf].y = Qs[(row + 8) * 68 + c];
      qf.a[kb][mf].z = Qs[ row      * 68 + c + 4];
      qf.a[kb][mf].w = Qs[(row + 8) * 68 + c + 4];
    }
  }

  const int wbase = T_ - 64 - t0;
  att_chunk_pro(Etf, Es, QE, qf, h, wbase,       wM, wN, g, tg, tid);
  att_chunk_pro(Etf, Es, QE, qf, h, wbase + 128, wM, wN, g, tg, tid);

  const unsigned ks_s = (unsigned)__cvta_generic_to_shared(Ks);
  const unsigned vs_s = (unsigned)__cvta_generic_to_shared(Vs);
  const unsigned es_s = (unsigned)__cvta_generic_to_shared(Es);
  const int ldp = tid >> 4;
  const int ldd = (tid & 15) * 4;

  {
#pragma unroll
    for (int p = 0; p < 8; p++) {
      const int e = p * 16 + ldp;
      const size_t gi = ((size_t)(b * T_ + e)) * HD + ldd;
      cpa16(ks_s + (unsigned)(e * 68 + ldd) * 4u, kh + gi);
      cpa16(vs_s + (unsigned)(e * 68 + ldd) * 4u, vh + gi);
    }
    CPA_COMMIT();
    const int cb = wbase + 256;
#pragma unroll
    for (int p = 0; p < 8; p++) {
      const int j = p * 16 + ldp;
      if (cb + j < T_)
        cpa16(es_s + (unsigned)(j * 68 + ldd) * 4u, Etf + ((size_t)(h * T_ + cb + j)) * HD + ldd);
      else
        *(uint4*)(Es + j * 68 + ldd) = make_uint4(0u, 0u, 0u, 0u);
    }
    CPA_COMMIT();
  }

  int trow[4];
  trow[0] = wM * 32 + g;      trow[1] = trow[0] + 8;
  trow[2] = trow[0] + 16;     trow[3] = trow[0] + 24;

  float mrun[4], lrun[4];
  float4 O[2][2];
#pragma unroll
  for (int i = 0; i < 4; i++) { mrun[i] = -1e30f; lrun[i] = 0.f; }
#pragma unroll
  for (int mf = 0; mf < 2; mf++)
#pragma unroll
    for (int nf = 0; nf < 2; nf++) O[mf][nf] = make_float4(0.f, 0.f, 0.f, 0.f);

  const int ns = (t0 + 64 + 127) >> 7;
  int cnext = wbase + 256;
  for (int it = 0; it < ns; it++) {
    const int s0 = it * 128;
    CPA_WAIT(1);
    __syncthreads();    // (A)

    float4 acc[2][4];
#pragma unroll
    for (int mf = 0; mf < 2; mf++)
#pragma unroll
      for (int nf = 0; nf < 4; nf++) acc[mf][nf] = make_float4(0.f, 0.f, 0.f, 0.f);
#pragma unroll
    for (int kb = 0; kb < 8; kb++) {
      const int kk = kb * 8;
#pragma unroll
      for (int nf = 0; nf < 4; nf++) {
        const int n = wN * 32 + nf * 8 + g;
        const unsigned b0 = Ks[n * 68 + kk + tg];
        const unsigned b1 = Ks[n * 68 + kk + tg + 4];
#pragma unroll
        for (int mf = 0; mf < 2; mf++)
          mma8(acc[mf][nf], qf.a[kb][mf].x, qf.a[kb][mf].y, qf.a[kb][mf].z, qf.a[kb][mf].w, b0, b1);
      }
    }

    float mx[4] = {-1e30f, -1e30f, -1e30f, -1e30f};
#pragma unroll
    for (int mf = 0; mf < 2; mf++) {
      const int tA = t0 + trow[mf * 2];
      const int tB = t0 + trow[mf * 2 + 1];
#pragma unroll
      for (int nf = 0; nf < 4; nf++) {
        const int s = s0 + wN * 32 + nf * 8 + 2 * tg;
        float4& a = acc[mf][nf];
        const float q0 = QE[ trow[mf*2]    * 260 + ((s     - tA + 2047) & 255)];
        const float q1 = QE[ trow[mf*2]    * 260 + ((s + 1 - tA + 2047) & 255)];
        const float q2 = QE[ trow[mf*2+1]  * 260 + ((s     - tB + 2047) & 255)];
        const float q3 = QE[ trow[mf*2+1]  * 260 + ((s + 1 - tB + 2047) & 255)];
        a.x = (s     <= tA) ? a.x + q0 : -1e30f;
        a.y = (s + 1 <= tA) ? a.y + q1 : -1e30f;
        a.z = (s     <= tB) ? a.z + q2 : -1e30f;
        a.w = (s + 1 <= tB) ? a.w + q3 : -1e30f;
        mx[mf*2]   = fmaxf(mx[mf*2],   fmaxf(a.x, a.y));
        mx[mf*2+1] = fmaxf(mx[mf*2+1], fmaxf(a.z, a.w));
      }
    }
#pragma unroll
    for (int i = 0; i < 4; i++) {
      mx[i] = fmaxf(mx[i], __shfl_xor_sync(0xffffffffu, mx[i], 1));
      mx[i] = fmaxf(mx[i], __shfl_xor_sync(0xffffffffu, mx[i], 2));
    }
    if (tg == 0) {
#pragma unroll
      for (int i = 0; i < 4; i++) sPmax[wN * 64 + trow[i]] = mx[i];
    }
    __syncthreads();    // (B)

    if (it + 1 < ns) {
      const int s1 = s0 + 128;
#pragma unroll
      for (int p = 0; p < 8; p++) {
        const int e = p * 16 + ldp;
        cpa16(ks_s + (unsigned)(e * 68 + ldd) * 4u,
              kh + ((size_t)(b * T_ + s1 + e)) * HD + ldd);
      }
    }
    CPA_COMMIT();

    float Mrow[4], alpha[4];
#pragma unroll
    for (int i = 0; i < 4; i++) {
      float M = mrun[i];
      M = fmaxf(M, sPmax[       trow[i]]);
      M = fmaxf(M, sPmax[ 64  + trow[i]]);
      M = fmaxf(M, sPmax[128  + trow[i]]);
      M = fmaxf(M, sPmax[192  + trow[i]]);
      alpha[i] = __expf(mrun[i] - M);
      mrun[i] = M;
      Mrow[i] = M;
    }

    float sm4[4] = {0.f, 0.f, 0.f, 0.f};
#pragma unroll
    for (int mf = 0; mf < 2; mf++) {
#pragma unroll
      for (int nf = 0; nf < 4; nf++) {
        float4& a = acc[mf][nf];
        const int col = wN * 32 + nf * 8 + 2 * tg;
        const float p0 = __expf(a.x - Mrow[mf*2]);
        const float p1 = __expf(a.y - Mrow[mf*2]);
        const float p2 = __expf(a.z - Mrow[mf*2+1]);
        const float p3 = __expf(a.w - Mrow[mf*2+1]);
        sm4[mf*2]   += p0 + p1;
        sm4[mf*2+1] += p2 + p3;
        Ps[ trow[mf*2]    * 132 + col    ] = f2tf(p0);
        Ps[ trow[mf*2]    * 132 + col + 1] = f2tf(p1);
        Ps[ trow[mf*2+1]  * 132 + col    ] = f2tf(p2);
        Ps[ trow[mf*2+1]  * 132 + col + 1] = f2tf(p3);
      }
    }
#pragma unroll
    for (int i = 0; i < 4; i++) {
      sm4[i] += __shfl_xor_sync(0xffffffffu, sm4[i], 1);
      sm4[i] += __shfl_xor_sync(0xffffffffu, sm4[i], 2);
    }
    if (tg == 0) {
#pragma unroll
      for (int i = 0; i < 4; i++) sPsum[wN * 64 + trow[i]] = sm4[i];
    }
    CPA_WAIT(1);
    __syncthreads();    // (C)
#pragma unroll
    for (int i = 0; i < 4; i++) {
      lrun[i] = lrun[i] * alpha[i]
              + sPsum[trow[i]] + sPsum[64 + trow[i]]
              + sPsum[128 + trow[i]] + sPsum[192 + trow[i]];
    }
#pragma unroll
    for (int mf = 0; mf < 2; mf++)
#pragma unroll
      for (int nf = 0; nf < 2; nf++) {
        O[mf][nf].x *= alpha[mf*2];   O[mf][nf].y *= alpha[mf*2];
        O[mf][nf].z *= alpha[mf*2+1]; O[mf][nf].w *= alpha[mf*2+1];
      }

#pragma unroll
    for (int kb = 0; kb < 16; kb++) {
      const int kk = kb * 8;
#pragma unroll
      for (int mf = 0; mf < 2; mf++) {
        const int r0 = trow[mf * 2];
        const unsigned a0 = Ps[ r0      * 132 + kk + tg];
        const unsigned a1 = Ps[(r0 + 8) * 132 + kk + tg];
        const unsigned a2 = Ps[ r0      * 132 + kk + tg + 4];
        const unsigned a3 = Ps[(r0 + 8) * 132 + kk + tg + 4];
#pragma unroll
        for (int nf = 0; nf < 2; nf++) {
          const int n = wN * 16 + nf * 8 + g;
          mma8(O[mf][nf], a0, a1, a2, a3, Vs[(kk + tg) * 68 + n], Vs[(kk + tg + 4) * 68 + n]);
        }
      }
    }

    if (cnext < T_) {
      float4 cacc[2][4];
#pragma unroll
      for (int mf = 0; mf < 2; mf++)
#pragma unroll
        for (int nf = 0; nf < 4; nf++) cacc[mf][nf] = make_float4(0.f, 0.f, 0.f, 0.f);
#pragma unroll
      for (int kb = 0; kb < 8; kb++) {
        const int kk = kb * 8;
#pragma unroll
        for (int nf = 0; nf < 4; nf++) {
          const int n = wN * 32 + nf * 8 + g;
          const unsigned b0 = Es[n * 68 + kk + tg];
          const unsigned b1 = Es[n * 68 + kk + tg + 4];
#pragma unroll
          for (int mf = 0; mf < 2; mf++)
            mma8(cacc[mf][nf], qf.a[kb][mf].x, qf.a[kb][mf].y, qf.a[kb][mf].z, qf.a[kb][mf].w, b0, b1);
        }
      }
#pragma unroll
      for (int mf = 0; mf < 2; mf++) {
        const int tl = wM * 32 + mf * 16 + g;
#pragma unroll
        for (int nf = 0; nf < 4; nf++) {
          const int r = cnext + wN * 32 + nf * 8 + 2 * tg;
          QE[ tl      * 260 + ( r      & 255)] = cacc[mf][nf].x;
          QE[ tl      * 260 + ((r + 1) & 255)] = cacc[mf][nf].y;
          QE[(tl + 8) * 260 + ( r      & 255)] = cacc[mf][nf].z;
          QE[(tl + 8) * 260 + ((r + 1) & 255)] = cacc[mf][nf].w;
        }
      }
    }
    __syncthreads();    // (D)

    if (it + 1 < ns) {
      const int s1 = s0 + 128;
#pragma unroll
      for (int p = 0; p < 8; p++) {
        const int e = p * 16 + ldp;
        cpa16(vs_s + (unsigned)(e * 68 + ldd) * 4u,
              vh + ((size_t)(b * T_ + s1 + e)) * HD + ldd);
      }
      const int cb2 = cnext + 128;
#pragma unroll
      for (int p = 0; p < 8; p++) {
        const int j = p * 16 + ldp;
        if (cb2 + j < T_)
          cpa16(es_s + (unsigned)(j * 68 + ldd) * 4u,
                Etf + ((size_t)(h * T_ + cb2 + j)) * HD + ldd);
        else
          *(uint4*)(Es + j * 68 + ldd) = make_uint4(0u, 0u, 0u, 0u);
      }
    }
    CPA_COMMIT();
    cnext += 128;
  }

  float inv[4];
#pragma unroll
  for (int i = 0; i < 4; i++) inv[i] = 1.f / lrun[i];
#pragma unroll
  for (int mf = 0; mf < 2; mf++) {
    const int tA = t0 + trow[mf * 2];
    const int tB = t0 + trow[mf * 2 + 1];
#pragma unroll
    for (int nf = 0; nf < 2; nf++) {
      const int c = h * HD + wN * 16 + nf * 8 + 2 * tg;
      uint2 o1 = make_uint2(f2tf(O[mf][nf].x * inv[mf*2]),   f2tf(O[mf][nf].y * inv[mf*2]));
      uint2 o2 = make_uint2(f2tf(O[mf][nf].z * inv[mf*2+1]), f2tf(O[mf][nf].w * inv[mf*2+1]));
      *(uint2*)&ctx[((size_t)(b * T_ + tA)) * DM + c] = o1;
      *(uint2*)&ctx[((size_t)(b * T_ + tB)) * DM + c] = o2;
    }
  }
}

// ---------------------------------------------------------------------------
extern "C" void kernel_launch(void* const* d_in, const int* in_sizes, int n_in,
                              void* d_out, int out_size) {
  const float* v  = (const float*)d_in[0];
  const float* k  = (const float*)d_in[1];
  const float* q  = (const float*)d_in[2];
  // d_in[3] = mask (causal tril; implicit)
  const float* Wq = (const float*)d_in[4];
  const float* bq = (const float*)d_in[5];
  const float* Wk = (const float*)d_in[6];
  const float* bk = (const float*)d_in[7];
  const float* Wv = (const float*)d_in[8];
  const float* bv = (const float*)d_in[9];
  const float* E  = (const float*)d_in[10];
  const float* Wo = (const float*)d_in[11];
  const float* bo = (const float*)d_in[12];
  const float* Wl = (const float*)d_in[13];
  const float* bl = (const float*)d_in[14];
  float* out = (float*)d_out;

  unsigned *qh, *kh, *vh, *Etf, *Wotf, *Wltf, *ctx, *hid;
  cudaGetSymbolAddress((void**)&qh,   g_qh);
  cudaGetSymbolAddress((void**)&kh,   g_kh);
  cudaGetSymbolAddress((void**)&vh,   g_vh);
  cudaGetSymbolAddress((void**)&Etf,  g_Etf);
  cudaGetSymbolAddress((void**)&Wotf, g_Wotf);
  cudaGetSymbolAddress((void**)&Wltf, g_Wltf);
  cudaGetSymbolAddress((void**)&ctx,  g_ctx);
  cudaGetSymbolAddress((void**)&hid,  g_hid);

  const int M = B_ * T_;
  dim3 blk(256);

  const int ncvt = NE4 + NWO4 + NWL4;   // 385024
  cvt_all<<<(ncvt + 255) / 256, blk>>>(E, Wo, Wl, Etf, Wotf, Wltf);
  proj4<<<dim3(M / 64, 1, 3), blk>>>(q, k, v, Wq, bq, Wk, bk, Wv, bv, qh, kh, vh);

  // smem words: Qs 4352 + Ks 8704 + Vs 8704 + Ps 8448 + Es 8704 + QE 16640 + red 512
  const size_t ATT_SMEM = (size_t)(4352 + 8704 + 8704 + 8448 + 8704 + 16640 + 512) * 4; // 224256 B
  cudaFuncSetAttribute(attn_kernel, cudaFuncAttributeMaxDynamicSharedMemorySize,
                       (int)ATT_SMEM);
  attn_kernel<<<dim3(T_ / 64, B_, NH), blk, ATT_SMEM>>>(qh, kh, vh, Etf, ctx);

  gemm4<true,  true ><<<dim3(M / 64, ED / 64), blk>>>(ctx, Wotf, bo, hid, M, ED, ED, DM, 1.f);
  gemm4<false, false><<<dim3(M / 64, EVP / 64), blk>>>(hid, Wltf, bl, out, M, EV, EVP, ED, 1.f);
}

// round 12
// speedup vs baseline: 1.0144x; 1.0144x over previous
#include <cuda_runtime.h>
#include <cstdint>

#define B_  2
#define T_  2048
#define HD  64
#define NH  8
#define DM  512
#define ED  512
#define EV  388
#define EVP 448      // Wl padded width

// ---------------- scratch ----------------
__device__ unsigned g_qh  [B_*T_*HD];   // tf32 bits, pre-scaled by 0.125
__device__ unsigned g_kh  [B_*T_*HD];   // tf32 bits
__device__ unsigned g_vh  [B_*T_*HD];   // tf32 bits
__device__ unsigned g_Etf [NH*T_*HD];   // tf32 bits
__device__ unsigned g_Wotf[DM*ED];      // tf32 bits
__device__ unsigned g_Wltf[ED*EVP];     // tf32 bits, zero-padded cols
__device__ unsigned g_ctx [B_*T_*DM];   // tf32 bits (attn out)
__device__ unsigned g_hid [B_*T_*ED];   // tf32 bits (relu out)

// ---------------- tf32 / async helpers ----------------
__device__ __forceinline__ unsigned f2tf(float f) {
  unsigned u; asm("cvt.rna.tf32.f32 %0, %1;" : "=r"(u) : "f"(f)); return u;
}
__device__ __forceinline__ unsigned u2tf(unsigned raw) {
  return f2tf(__uint_as_float(raw));
}
__device__ __forceinline__ void mma8(float4& d, unsigned a0, unsigned a1, unsigned a2, unsigned a3,
                                     unsigned b0, unsigned b1) {
  asm volatile("mma.sync.aligned.m16n8k8.row.col.f32.tf32.tf32.f32 "
               "{%0,%1,%2,%3}, {%4,%5,%6,%7}, {%8,%9}, {%0,%1,%2,%3};"
               : "+f"(d.x), "+f"(d.y), "+f"(d.z), "+f"(d.w)
               : "r"(a0), "r"(a1), "r"(a2), "r"(a3), "r"(b0), "r"(b1));
}
__device__ __forceinline__ void cpa16(unsigned smem, const void* g) {
  asm volatile("cp.async.cg.shared.global [%0], [%1], 16;" :: "r"(smem), "l"(g));
}
#define CPA_COMMIT() asm volatile("cp.async.commit_group;")
#define CPA_WAIT(N)  asm volatile("cp.async.wait_group %0;" :: "n"(N) : "memory")
__device__ __forceinline__ void cpa_wait_all() {
  CPA_COMMIT(); CPA_WAIT(0);
}

// ---------------- sizes for fused converter ----------------
#define NE4  (NH*T_*HD/4)    // 262144
#define NWO4 (DM*ED/4)       // 65536
#define NWL4 (ED*EVP/4)      // 57344
#define NCVT (NE4 + NWO4 + NWL4)          // 385024
#define CVT_BLKS ((NCVT + 255) / 256)     // 1504
#define PROJ_BLKS 192

// ================= gemm3: all-tf32-in, 3-stage cp.async (verified 263.5) ===
// CTA 128x64, 8 warps 4(m)x2(n), warp m32 x n32, k16 per stage.
#define G3S 3648   // words per stage: A 128*20=2560 + B 16*68=1088
template<bool RELU, bool TF32OUT>
__launch_bounds__(256)
__global__ void gemm3(const unsigned* __restrict__ A, const unsigned* __restrict__ Bm,
                      const float* __restrict__ bias, void* __restrict__ Cv,
                      int M, int N, int Np, int K, float oscale) {
  __shared__ unsigned sm[3 * G3S];
  const int tid = threadIdx.x;
  const int lane = tid & 31, wid = tid >> 5;
  const int wM = wid & 3, wN = wid >> 2;
  const int g = lane >> 2, tg = lane & 3;
  const int m0 = blockIdx.x * 128, n0 = blockIdx.y * 64;
  const int ai0 = tid * 2, ai1 = ai0 + 1;
  const int ar0 = ai0 >> 2, ac0 = (ai0 & 3) * 4;
  const int ar1 = ai1 >> 2, ac1 = (ai1 & 3) * 4;
  const int bk = tid >> 4, bn = (tid & 15) * 4;
  const unsigned s_base = (unsigned)__cvta_generic_to_shared(sm);

  const int NT = K >> 4;
#define G3_ISSUE(KT) do {                                                     \
    const int _k0 = (KT) * 16;                                                \
    const unsigned _st = s_base + ((KT) % 3) * (G3S * 4);                     \
    cpa16(_st + (unsigned)(ar0*20+ac0)*4u, A + (size_t)(m0+ar0)*K + _k0+ac0); \
    cpa16(_st + (unsigned)(ar1*20+ac1)*4u, A + (size_t)(m0+ar1)*K + _k0+ac1); \
    cpa16(_st + (unsigned)(2560 + bk*68+bn)*4u,                               \
          Bm + (size_t)(_k0+bk)*Np + n0+bn);                                  \
  } while (0)

  G3_ISSUE(0); CPA_COMMIT();
  G3_ISSUE(1); CPA_COMMIT();

  float4 acc[2][4];
#pragma unroll
  for (int mf = 0; mf < 2; mf++)
#pragma unroll
    for (int nf = 0; nf < 4; nf++) acc[mf][nf] = make_float4(0.f, 0.f, 0.f, 0.f);

  for (int kt = 0; kt < NT; kt++) {
    CPA_WAIT(1);
    __syncthreads();
    if (kt + 2 < NT) G3_ISSUE(kt + 2);
    CPA_COMMIT();
    const unsigned* Ac = sm + (kt % 3) * G3S;
    const unsigned* Bc = Ac + 2560;
#pragma unroll
    for (int kb = 0; kb < 2; kb++) {
      const int kk = kb * 8;
      uint4 af[2];
#pragma unroll
      for (int mf = 0; mf < 2; mf++) {
        const int r = wM * 32 + mf * 16 + g;
        af[mf].x = Ac[ r      * 20 + kk + tg];
        af[mf].y = Ac[(r + 8) * 20 + kk + tg];
        af[mf].z = Ac[ r      * 20 + kk + tg + 4];
        af[mf].w = Ac[(r + 8) * 20 + kk + tg + 4];
      }
#pragma unroll
      for (int nf = 0; nf < 4; nf++) {
        const int n = wN * 32 + nf * 8 + g;
        const unsigned b0 = Bc[(kk + tg) * 68 + n];
        const unsigned b1 = Bc[(kk + tg + 4) * 68 + n];
#pragma unroll
        for (int mf = 0; mf < 2; mf++)
          mma8(acc[mf][nf], af[mf].x, af[mf].y, af[mf].z, af[mf].w, b0, b1);
      }
    }
  }

#pragma unroll
  for (int mf = 0; mf < 2; mf++) {
    const int r1 = m0 + wM * 32 + mf * 16 + g, r2 = r1 + 8;
#pragma unroll
    for (int nf = 0; nf < 4; nf++) {
      const int c = n0 + wN * 32 + nf * 8 + 2 * tg;
      const float4 a = acc[mf][nf];
      if (c < N) {
        const float bv = bias[c];
        float v1 = a.x + bv, v2 = a.z + bv;
        if (RELU) { v1 = fmaxf(v1, 0.f); v2 = fmaxf(v2, 0.f); }
        if (TF32OUT) {
          ((unsigned*)Cv)[(size_t)r1 * N + c] = f2tf(v1 * oscale);
          ((unsigned*)Cv)[(size_t)r2 * N + c] = f2tf(v2 * oscale);
        } else {
          ((float*)Cv)[(size_t)r1 * N + c] = v1;
          ((float*)Cv)[(size_t)r2 * N + c] = v2;
        }
      }
      if (c + 1 < N) {
        const float bv = bias[c + 1];
        float v1 = a.y + bv, v2 = a.w + bv;
        if (RELU) { v1 = fmaxf(v1, 0.f); v2 = fmaxf(v2, 0.f); }
        if (TF32OUT) {
          ((unsigned*)Cv)[(size_t)r1 * N + c + 1] = f2tf(v1 * oscale);
          ((unsigned*)Cv)[(size_t)r2 * N + c + 1] = f2tf(v2 * oscale);
        } else {
          ((float*)Cv)[(size_t)r1 * N + c + 1] = v1;
          ((float*)Cv)[(size_t)r2 * N + c + 1] = v2;
        }
      }
    }
  }
#undef G3_ISSUE
}

// ================= prep: fused q/k/v projection (m64 tiles) + converters ===
// blocks [0,192): proj (bz = bx/64 selects q/k/v, m-tile = bx%64)
// blocks [192, 192+1504): elementwise tf32 conversion of E / Wo / Wl.
#define P4S 2368   // words per stage: A 64*20=1280 + B 16*68=1088
__launch_bounds__(256)
__global__ void prep_kernel(const float* __restrict__ q, const float* __restrict__ k,
                            const float* __restrict__ v,
                            const float* __restrict__ Wq, const float* __restrict__ bq,
                            const float* __restrict__ Wk, const float* __restrict__ bk2,
                            const float* __restrict__ Wv, const float* __restrict__ bv2,
                            unsigned* __restrict__ qh, unsigned* __restrict__ kh,
                            unsigned* __restrict__ vh,
                            const float* __restrict__ E, const float* __restrict__ Wo,
                            const float* __restrict__ Wl,
                            unsigned* __restrict__ Etf, unsigned* __restrict__ Wotf,
                            unsigned* __restrict__ Wltf) {
  __shared__ unsigned sm[3 * P4S];
  const int bx = blockIdx.x;

  if (bx >= PROJ_BLKS) {   // ---- converter part ----
    const int i = (bx - PROJ_BLKS) * 256 + threadIdx.x;
    if (i < NE4) {
      float4 f = ((const float4*)E)[i];
      ((uint4*)Etf)[i] = make_uint4(f2tf(f.x), f2tf(f.y), f2tf(f.z), f2tf(f.w));
    } else if (i < NE4 + NWO4) {
      const int j = i - NE4;
      float4 f = ((const float4*)Wo)[j];
      ((uint4*)Wotf)[j] = make_uint4(f2tf(f.x), f2tf(f.y), f2tf(f.z), f2tf(f.w));
    } else if (i < NCVT) {
      const int j = i - NE4 - NWO4;
      const int row = (j * 4) / EVP, col = (j * 4) % EVP;
      uint4 u = make_uint4(0u, 0u, 0u, 0u);
      if (col < EV) {
        float4 f = *(const float4*)(Wl + (size_t)row * EV + col);
        u = make_uint4(f2tf(f.x), f2tf(f.y), f2tf(f.z), f2tf(f.w));
      }
      ((uint4*)Wltf)[j] = u;
    }
    return;
  }

  // ---- projection part ----
  const int bz = bx >> 6;
  const float* A; const float* Bm; const float* Bi; unsigned* Cc; float sc;
  if (bz == 0)      { A = q; Bm = Wq; Bi = bq;  Cc = qh; sc = 0.125f; }
  else if (bz == 1) { A = k; Bm = Wk; Bi = bk2; Cc = kh; sc = 1.f; }
  else              { A = v; Bm = Wv; Bi = bv2; Cc = vh; sc = 1.f; }

  const int tid = threadIdx.x;
  const int lane = tid & 31, wid = tid >> 5;
  const int wM = wid & 3, wN = wid >> 2;
  const int g = lane >> 2, tg = lane & 3;
  const int m0 = (bx & 63) * 64;
  const int ar = tid >> 2, ac = (tid & 3) * 4;
  const int bk = tid >> 4, bn = (tid & 15) * 4;
  const unsigned s_base = (unsigned)__cvta_generic_to_shared(sm);

  const int NT = DM >> 4;   // 32
#define P4_ISSUE(KT) do {                                                       \
    const int _k0 = (KT) * 16;                                                  \
    const unsigned _st = s_base + ((KT) % 3) * (P4S * 4);                       \
    cpa16(_st + (unsigned)(ar*20+ac)*4u, A + (size_t)(m0+ar)*DM + _k0+ac);      \
    cpa16(_st + (unsigned)(1280 + bk*68+bn)*4u, Bm + (size_t)(_k0+bk)*HD + bn); \
  } while (0)

  P4_ISSUE(0); CPA_COMMIT();
  P4_ISSUE(1); CPA_COMMIT();

  float4 acc[4];
#pragma unroll
  for (int nf = 0; nf < 4; nf++) acc[nf] = make_float4(0.f, 0.f, 0.f, 0.f);

  for (int kt = 0; kt < NT; kt++) {
    CPA_WAIT(1);
    __syncthreads();
    if (kt + 2 < NT) P4_ISSUE(kt + 2);
    CPA_COMMIT();
    const unsigned* Ac = sm + (kt % 3) * P4S;
    const unsigned* Bc = Ac + 1280;
#pragma unroll
    for (int kb = 0; kb < 2; kb++) {
      const int kk = kb * 8;
      const int r = wM * 16 + g;
      const unsigned a0 = u2tf(Ac[ r      * 20 + kk + tg]);
      const unsigned a1 = u2tf(Ac[(r + 8) * 20 + kk + tg]);
      const unsigned a2 = u2tf(Ac[ r      * 20 + kk + tg + 4]);
      const unsigned a3 = u2tf(Ac[(r + 8) * 20 + kk + tg + 4]);
#pragma unroll
      for (int nf = 0; nf < 4; nf++) {
        const int n = wN * 32 + nf * 8 + g;
        const unsigned b0 = u2tf(Bc[(kk + tg) * 68 + n]);
        const unsigned b1 = u2tf(Bc[(kk + tg + 4) * 68 + n]);
        mma8(acc[nf], a0, a1, a2, a3, b0, b1);
      }
    }
  }

  {
    const int r1 = m0 + wM * 16 + g, r2 = r1 + 8;
#pragma unroll
    for (int nf = 0; nf < 4; nf++) {
      const int c = wN * 32 + nf * 8 + 2 * tg;   // always < 64
      const float4 a = acc[nf];
      const float bv0 = Bi[c], bv1 = Bi[c + 1];
      Cc[(size_t)r1 * HD + c]     = f2tf((a.x + bv0) * sc);
      Cc[(size_t)r2 * HD + c]     = f2tf((a.z + bv0) * sc);
      Cc[(size_t)r1 * HD + c + 1] = f2tf((a.y + bv1) * sc);
      Cc[(size_t)r2 * HD + c + 1] = f2tf((a.w + bv1) * sc);
    }
  }
#undef P4_ISSUE
}

// ===================== attention: pipelined loads (verified 263.5) =========
struct QFrag { uint4 a[8][2]; };

__device__ __forceinline__ void att_chunk_pro(const unsigned* __restrict__ Etf, unsigned* Es,
                                              float* QE, const QFrag& qf, int h, int cb,
                                              int wM, int wN, int g, int tg, int tid) {
  if (cb >= T_) return;
  const unsigned es_s = (unsigned)__cvta_generic_to_shared(Es);
#pragma unroll
  for (int p = 0; p < 8; p++) {
    const int j = p * 16 + (tid >> 4);
    const int d = (tid & 15) * 4;
    if (cb + j < T_)
      cpa16(es_s + (unsigned)(j * 68 + d) * 4u, Etf + ((size_t)(h * T_ + cb + j)) * HD + d);
    else
      *(uint4*)(Es + j * 68 + d) = make_uint4(0u, 0u, 0u, 0u);
  }
  cpa_wait_all();
  __syncthreads();
  float4 acc[2][4];
#pragma unroll
  for (int mf = 0; mf < 2; mf++)
#pragma unroll
    for (int nf = 0; nf < 4; nf++) acc[mf][nf] = make_float4(0.f, 0.f, 0.f, 0.f);
#pragma unroll
  for (int kb = 0; kb < 8; kb++) {
    const int kk = kb * 8;
#pragma unroll
    for (int nf = 0; nf < 4; nf++) {
      const int n = wN * 32 + nf * 8 + g;
      const unsigned b0 = Es[n * 68 + kk + tg];
      const unsigned b1 = Es[n * 68 + kk + tg + 4];
#pragma unroll
      for (int mf = 0; mf < 2; mf++)
        mma8(acc[mf][nf], qf.a[kb][mf].x, qf.a[kb][mf].y, qf.a[kb][mf].z, qf.a[kb][mf].w, b0, b1);
    }
  }
#pragma unroll
  for (int mf = 0; mf < 2; mf++) {
    const int tl = wM * 32 + mf * 16 + g;
#pragma unroll
    for (int nf = 0; nf < 4; nf++) {
      const int r = cb + wN * 32 + nf * 8 + 2 * tg;
      QE[ tl      * 260 + ( r      & 255)] = acc[mf][nf].x;
      QE[ tl      * 260 + ((r + 1) & 255)] = acc[mf][nf].y;
      QE[(tl + 8) * 260 + ( r      & 255)] = acc[mf][nf].z;
      QE[(tl + 8) * 260 + ((r + 1) & 255)] = acc[mf][nf].w;
    }
  }
  __syncthreads();
}

__launch_bounds__(256, 1)
__global__ void attn_kernel(const unsigned* __restrict__ qh, const unsigned* __restrict__ kh,
                            const unsigned* __restrict__ vh, const unsigned* __restrict__ Etf,
                            unsigned* __restrict__ ctx) {
  extern __shared__ unsigned smu[];
  unsigned* Qs = smu;                     // [64][68]
  unsigned* Ks = Qs + 4352;               // [128][68]
  unsigned* Vs = Ks + 8704;               // [128][68]
  unsigned* Ps = Vs + 8704;               // [64][132] P matrix
  unsigned* Es = Ps + 8448;               // [128][68] E chunk (dedicated)
  float*    QE = (float*)(Es + 8704);     // [64][260] ring
  float* sPmax = QE + 64 * 260;           // [4][64]
  float* sPsum = sPmax + 256;             // [4][64]

  const int tid = threadIdx.x;
  const int lane = tid & 31, wid = tid >> 5;
  const int wM = wid & 1, wN = wid >> 1;       // 2 x 4
  const int g = lane >> 2, tg = lane & 3;
  const int qt = (int)gridDim.x - 1 - (int)blockIdx.x;  // heavy tiles first
  const int t0 = qt * 64;
  const int b  = blockIdx.y;
  const int h  = blockIdx.z;

  {
    const unsigned qs_s = (unsigned)__cvta_generic_to_shared(Qs);
#pragma unroll
    for (int p = 0; p < 4; p++) {
      const int t = p * 16 + (tid >> 4);
      const int d = (tid & 15) * 4;
      cpa16(qs_s + (unsigned)(t * 68 + d) * 4u, qh + ((size_t)(b * T_ + t0 + t)) * HD + d);
    }
    cpa_wait_all();
  }
  __syncthreads();
  QFrag qf;
#pragma unroll
  for (int kb = 0; kb < 8; kb++) {
    const int c = kb * 8 + tg;
#pragma unroll
    for (int mf = 0; mf < 2; mf++) {
      const int row = wM * 32 + mf * 16 + g;
      qf.a[kb][mf].x = Qs[ row      * 68 + c];
      qf.a[kb][mf].y = Qs[(row + 8) * 68 + c];
      qf.a[kb][mf].z = Qs[ row      * 68 + c + 4];
      qf.a[kb][mf].w = Qs[(row + 8) * 68 + c + 4];
    }
  }

  const int wbase = T_ - 64 - t0;
  att_chunk_pro(Etf, Es, QE, qf, h, wbase,       wM, wN, g, tg, tid);
  att_chunk_pro(Etf, Es, QE, qf, h, wbase + 128, wM, wN, g, tg, tid);

  const unsigned ks_s = (unsigned)__cvta_generic_to_shared(Ks);
  const unsigned vs_s = (unsigned)__cvta_generic_to_shared(Vs);
  const unsigned es_s = (unsigned)__cvta_generic_to_shared(Es);
  const int ldp = tid >> 4;
  const int ldd = (tid & 15) * 4;

  {
#pragma unroll
    for (int p = 0; p < 8; p++) {
      const int e = p * 16 + ldp;
      const size_t gi = ((size_t)(b * T_ + e)) * HD + ldd;
      cpa16(ks_s + (unsigned)(e * 68 + ldd) * 4u, kh + gi);
      cpa16(vs_s + (unsigned)(e * 68 + ldd) * 4u, vh + gi);
    }
    CPA_COMMIT();
    const int cb = wbase + 256;
#pragma unroll
    for (int p = 0; p < 8; p++) {
      const int j = p * 16 + ldp;
      if (cb + j < T_)
        cpa16(es_s + (unsigned)(j * 68 + ldd) * 4u, Etf + ((size_t)(h * T_ + cb + j)) * HD + ldd);
      else
        *(uint4*)(Es + j * 68 + ldd) = make_uint4(0u, 0u, 0u, 0u);
    }
    CPA_COMMIT();
  }

  int trow[4];
  trow[0] = wM * 32 + g;      trow[1] = trow[0] + 8;
  trow[2] = trow[0] + 16;     trow[3] = trow[0] + 24;

  float mrun[4], lrun[4];
  float4 O[2][2];
#pragma unroll
  for (int i = 0; i < 4; i++) { mrun[i] = -1e30f; lrun[i] = 0.f; }
#pragma unroll
  for (int mf = 0; mf < 2; mf++)
#pragma unroll
    for (int nf = 0; nf < 2; nf++) O[mf][nf] = make_float4(0.f, 0.f, 0.f, 0.f);

  const int ns = (t0 + 64 + 127) >> 7;
  int cnext = wbase + 256;
  for (int it = 0; it < ns; it++) {
    const int s0 = it * 128;
    CPA_WAIT(1);
    __syncthreads();    // (A)

    float4 acc[2][4];
#pragma unroll
    for (int mf = 0; mf < 2; mf++)
#pragma unroll
      for (int nf = 0; nf < 4; nf++) acc[mf][nf] = make_float4(0.f, 0.f, 0.f, 0.f);
#pragma unroll
    for (int kb = 0; kb < 8; kb++) {
      const int kk = kb * 8;
#pragma unroll
      for (int nf = 0; nf < 4; nf++) {
        const int n = wN * 32 + nf * 8 + g;
        const unsigned b0 = Ks[n * 68 + kk + tg];
        const unsigned b1 = Ks[n * 68 + kk + tg + 4];
#pragma unroll
        for (int mf = 0; mf < 2; mf++)
          mma8(acc[mf][nf], qf.a[kb][mf].x, qf.a[kb][mf].y, qf.a[kb][mf].z, qf.a[kb][mf].w, b0, b1);
      }
    }

    float mx[4] = {-1e30f, -1e30f, -1e30f, -1e30f};
#pragma unroll
    for (int mf = 0; mf < 2; mf++) {
      const int tA = t0 + trow[mf * 2];
      const int tB = t0 + trow[mf * 2 + 1];
#pragma unroll
      for (int nf = 0; nf < 4; nf++) {
        const int s = s0 + wN * 32 + nf * 8 + 2 * tg;
        float4& a = acc[mf][nf];
        const float q0 = QE[ trow[mf*2]    * 260 + ((s     - tA + 2047) & 255)];
        const float q1 = QE[ trow[mf*2]    * 260 + ((s + 1 - tA + 2047) & 255)];
        const float q2 = QE[ trow[mf*2+1]  * 260 + ((s     - tB + 2047) & 255)];
        const float q3 = QE[ trow[mf*2+1]  * 260 + ((s + 1 - tB + 2047) & 255)];
        a.x = (s     <= tA) ? a.x + q0 : -1e30f;
        a.y = (s + 1 <= tA) ? a.y + q1 : -1e30f;
        a.z = (s     <= tB) ? a.z + q2 : -1e30f;
        a.w = (s + 1 <= tB) ? a.w + q3 : -1e30f;
        mx[mf*2]   = fmaxf(mx[mf*2],   fmaxf(a.x, a.y));
        mx[mf*2+1] = fmaxf(mx[mf*2+1], fmaxf(a.z, a.w));
      }
    }
#pragma unroll
    for (int i = 0; i < 4; i++) {
      mx[i] = fmaxf(mx[i], __shfl_xor_sync(0xffffffffu, mx[i], 1));
      mx[i] = fmaxf(mx[i], __shfl_xor_sync(0xffffffffu, mx[i], 2));
    }
    if (tg == 0) {
#pragma unroll
      for (int i = 0; i < 4; i++) sPmax[wN * 64 + trow[i]] = mx[i];
    }
    __syncthreads();    // (B)

    if (it + 1 < ns) {
      const int s1 = s0 + 128;
#pragma unroll
      for (int p = 0; p < 8; p++) {
        const int e = p * 16 + ldp;
        cpa16(ks_s + (unsigned)(e * 68 + ldd) * 4u,
              kh + ((size_t)(b * T_ + s1 + e)) * HD + ldd);
      }
    }
    CPA_COMMIT();

    float Mrow[4], alpha[4];
#pragma unroll
    for (int i = 0; i < 4; i++) {
      float M = mrun[i];
      M = fmaxf(M, sPmax[       trow[i]]);
      M = fmaxf(M, sPmax[ 64  + trow[i]]);
      M = fmaxf(M, sPmax[128  + trow[i]]);
      M = fmaxf(M, sPmax[192  + trow[i]]);
      alpha[i] = __expf(mrun[i] - M);
      mrun[i] = M;
      Mrow[i] = M;
    }

    float sm4[4] = {0.f, 0.f, 0.f, 0.f};
#pragma unroll
    for (int mf = 0; mf < 2; mf++) {
#pragma unroll
      for (int nf = 0; nf < 4; nf++) {
        float4& a = acc[mf][nf];
        const int col = wN * 32 + nf * 8 + 2 * tg;
        const float p0 = __expf(a.x - Mrow[mf*2]);
        const float p1 = __expf(a.y - Mrow[mf*2]);
        const float p2 = __expf(a.z - Mrow[mf*2+1]);
        const float p3 = __expf(a.w - Mrow[mf*2+1]);
        sm4[mf*2]   += p0 + p1;
        sm4[mf*2+1] += p2 + p3;
        Ps[ trow[mf*2]    * 132 + col    ] = f2tf(p0);
        Ps[ trow[mf*2]    * 132 + col + 1] = f2tf(p1);
        Ps[ trow[mf*2+1]  * 132 + col    ] = f2tf(p2);
        Ps[ trow[mf*2+1]  * 132 + col + 1] = f2tf(p3);
      }
    }
#pragma unroll
    for (int i = 0; i < 4; i++) {
      sm4[i] += __shfl_xor_sync(0xffffffffu, sm4[i], 1);
      sm4[i] += __shfl_xor_sync(0xffffffffu, sm4[i], 2);
    }
    if (tg == 0) {
#pragma unroll
      for (int i = 0; i < 4; i++) sPsum[wN * 64 + trow[i]] = sm4[i];
    }
    CPA_WAIT(1);
    __syncthreads();    // (C)
#pragma unroll
    for (int i = 0; i < 4; i++) {
      lrun[i] = lrun[i] * alpha[i]
              + sPsum[trow[i]] + sPsum[64 + trow[i]]
              + sPsum[128 + trow[i]] + sPsum[192 + trow[i]];
    }
#pragma unroll
    for (int mf = 0; mf < 2; mf++)
#pragma unroll
      for (int nf = 0; nf < 2; nf++) {
        O[mf][nf].x *= alpha[mf*2];   O[mf][nf].y *= alpha[mf*2];
        O[mf][nf].z *= alpha[mf*2+1]; O[mf][nf].w *= alpha[mf*2+1];
      }

    // ---- PV: Vs fragments hoisted, shared across mf ----
#pragma unroll
    for (int kb = 0; kb < 16; kb++) {
      const int kk = kb * 8;
      uint2 bf[2];
#pragma unroll
      for (int nf = 0; nf < 2; nf++) {
        const int n = wN * 16 + nf * 8 + g;
        bf[nf].x = Vs[(kk + tg) * 68 + n];
        bf[nf].y = Vs[(kk + tg + 4) * 68 + n];
      }
#pragma unroll
      for (int mf = 0; mf < 2; mf++) {
        const int r0 = trow[mf * 2];
        const unsigned a0 = Ps[ r0      * 132 + kk + tg];
        const unsigned a1 = Ps[(r0 + 8) * 132 + kk + tg];
        const unsigned a2 = Ps[ r0      * 132 + kk + tg + 4];
        const unsigned a3 = Ps[(r0 + 8) * 132 + kk + tg + 4];
#pragma unroll
        for (int nf = 0; nf < 2; nf++)
          mma8(O[mf][nf], a0, a1, a2, a3, bf[nf].x, bf[nf].y);
      }
    }

    if (cnext < T_) {
      float4 cacc[2][4];
#pragma unroll
      for (int mf = 0; mf < 2; mf++)
#pragma unroll
        for (int nf = 0; nf < 4; nf++) cacc[mf][nf] = make_float4(0.f, 0.f, 0.f, 0.f);
#pragma unroll
      for (int kb = 0; kb < 8; kb++) {
        const int kk = kb * 8;
#pragma unroll
        for (int nf = 0; nf < 4; nf++) {
          const int n = wN * 32 + nf * 8 + g;
          const unsigned b0 = Es[n * 68 + kk + tg];
          const unsigned b1 = Es[n * 68 + kk + tg + 4];
#pragma unroll
          for (int mf = 0; mf < 2; mf++)
            mma8(cacc[mf][nf], qf.a[kb][mf].x, qf.a[kb][mf].y, qf.a[kb][mf].z, qf.a[kb][mf].w, b0, b1);
        }
      }
#pragma unroll
      for (int mf = 0; mf < 2; mf++) {
        const int tl = wM * 32 + mf * 16 + g;
#pragma unroll
        for (int nf = 0; nf < 4; nf++) {
          const int r = cnext + wN * 32 + nf * 8 + 2 * tg;
          QE[ tl      * 260 + ( r      & 255)] = cacc[mf][nf].x;
          QE[ tl      * 260 + ((r + 1) & 255)] = cacc[mf][nf].y;
          QE[(tl + 8) * 260 + ( r      & 255)] = cacc[mf][nf].z;
          QE[(tl + 8) * 260 + ((r + 1) & 255)] = cacc[mf][nf].w;
        }
      }
    }
    __syncthreads();    // (D)

    if (it + 1 < ns) {
      const int s1 = s0 + 128;
#pragma unroll
      for (int p = 0; p < 8; p++) {
        const int e = p * 16 + ldp;
        cpa16(vs_s + (unsigned)(e * 68 + ldd) * 4u,
              vh + ((size_t)(b * T_ + s1 + e)) * HD + ldd);
      }
      const int cb2 = cnext + 128;
#pragma unroll
      for (int p = 0; p < 8; p++) {
        const int j = p * 16 + ldp;
        if (cb2 + j < T_)
          cpa16(es_s + (unsigned)(j * 68 + ldd) * 4u,
                Etf + ((size_t)(h * T_ + cb2 + j)) * HD + ldd);
        else
          *(uint4*)(Es + j * 68 + ldd) = make_uint4(0u, 0u, 0u, 0u);
      }
    }
    CPA_COMMIT();
    cnext += 128;
  }

  float inv[4];
#pragma unroll
  for (int i = 0; i < 4; i++) inv[i] = 1.f / lrun[i];
#pragma unroll
  for (int mf = 0; mf < 2; mf++) {
    const int tA = t0 + trow[mf * 2];
    const int tB = t0 + trow[mf * 2 + 1];
#pragma unroll
    for (int nf = 0; nf < 2; nf++) {
      const int c = h * HD + wN * 16 + nf * 8 + 2 * tg;
      uint2 o1 = make_uint2(f2tf(O[mf][nf].x * inv[mf*2]),   f2tf(O[mf][nf].y * inv[mf*2]));
      uint2 o2 = make_uint2(f2tf(O[mf][nf].z * inv[mf*2+1]), f2tf(O[mf][nf].w * inv[mf*2+1]));
      *(uint2*)&ctx[((size_t)(b * T_ + tA)) * DM + c] = o1;
      *(uint2*)&ctx[((size_t)(b * T_ + tB)) * DM + c] = o2;
    }
  }
}

// ---------------------------------------------------------------------------
extern "C" void kernel_launch(void* const* d_in, const int* in_sizes, int n_in,
                              void* d_out, int out_size) {
  const float* v  = (const float*)d_in[0];
  const float* k  = (const float*)d_in[1];
  const float* q  = (const float*)d_in[2];
  // d_in[3] = mask (causal tril; implicit)
  const float* Wq = (const float*)d_in[4];
  const float* bq = (const float*)d_in[5];
  const float* Wk = (const float*)d_in[6];
  const float* bk = (const float*)d_in[7];
  const float* Wv = (const float*)d_in[8];
  const float* bv = (const float*)d_in[9];
  const float* E  = (const float*)d_in[10];
  const float* Wo = (const float*)d_in[11];
  const float* bo = (const float*)d_in[12];
  const float* Wl = (const float*)d_in[13];
  const float* bl = (const float*)d_in[14];
  float* out = (float*)d_out;

  unsigned *qh, *kh, *vh, *Etf, *Wotf, *Wltf, *ctx, *hid;
  cudaGetSymbolAddress((void**)&qh,   g_qh);
  cudaGetSymbolAddress((void**)&kh,   g_kh);
  cudaGetSymbolAddress((void**)&vh,   g_vh);
  cudaGetSymbolAddress((void**)&Etf,  g_Etf);
  cudaGetSymbolAddress((void**)&Wotf, g_Wotf);
  cudaGetSymbolAddress((void**)&Wltf, g_Wltf);
  cudaGetSymbolAddress((void**)&ctx,  g_ctx);
  cudaGetSymbolAddress((void**)&hid,  g_hid);

  const int M = B_ * T_;
  dim3 blk(256);

  prep_kernel<<<PROJ_BLKS + CVT_BLKS, blk>>>(q, k, v, Wq, bq, Wk, bk, Wv, bv,
                                             qh, kh, vh, E, Wo, Wl, Etf, Wotf, Wltf);

  // smem words: Qs 4352 + Ks 8704 + Vs 8704 + Ps 8448 + Es 8704 + QE 16640 + red 512
  const size_t ATT_SMEM = (size_t)(4352 + 8704 + 8704 + 8448 + 8704 + 16640 + 512) * 4; // 224256 B
  cudaFuncSetAttribute(attn_kernel, cudaFuncAttributeMaxDynamicSharedMemorySize,
                       (int)ATT_SMEM);
  attn_kernel<<<dim3(T_ / 64, B_, NH), blk, ATT_SMEM>>>(qh, kh, vh, Etf, ctx);

  gemm3<true,  true ><<<dim3(M / 128, ED / 64), blk>>>(ctx, Wotf, bo, hid, M, ED, ED, DM, 1.f);
  gemm3<false, false><<<dim3(M / 128, EVP / 64), blk>>>(hid, Wltf, bl, out, M, EV, EVP, ED, 1.f);
}